// round 1
// baseline (speedup 1.0000x reference)
#include <cuda_runtime.h>
#include <cuda_bf16.h>

// Cosine similarity + segmented mean.
// x1, x2: [N, L*C] fp32 with L*C = 65536 (fixed for this problem).
// out: [N/n] fp32, mean over consecutive groups of n cosine similarities.

#define VEC_D      65536            // L*C
#define VEC_D4     (VEC_D / 4)      // float4 count per sample = 16384
#define T1         512              // threads per CTA in stage 1
#define MAX_SAMPLES 1024            // scratch capacity (N = 512 here)

// Scratch: dot, n1, n2 per sample. __device__ global (no allocation).
__device__ float g_dot[MAX_SAMPLES];
__device__ float g_n1[MAX_SAMPLES];
__device__ float g_n2[MAX_SAMPLES];

__device__ __forceinline__ float warp_sum(float v) {
    #pragma unroll
    for (int off = 16; off > 0; off >>= 1)
        v += __shfl_xor_sync(0xFFFFFFFFu, v, off);
    return v;
}

__global__ void __launch_bounds__(T1)
cos_stage1(const float* __restrict__ x1, const float* __restrict__ x2) {
    const int s = blockIdx.x;
    const float4* __restrict__ a =
        reinterpret_cast<const float4*>(x1) + (size_t)s * VEC_D4;
    const float4* __restrict__ b =
        reinterpret_cast<const float4*>(x2) + (size_t)s * VEC_D4;

    float dot = 0.0f, n1 = 0.0f, n2 = 0.0f;

    // 16384 float4 / 512 threads = 32 iterations. Unroll by 4 for MLP.
    #pragma unroll 4
    for (int i = threadIdx.x; i < VEC_D4; i += T1) {
        float4 av = a[i];
        float4 bv = b[i];
        dot = fmaf(av.x, bv.x, dot);
        dot = fmaf(av.y, bv.y, dot);
        dot = fmaf(av.z, bv.z, dot);
        dot = fmaf(av.w, bv.w, dot);
        n1  = fmaf(av.x, av.x, n1);
        n1  = fmaf(av.y, av.y, n1);
        n1  = fmaf(av.z, av.z, n1);
        n1  = fmaf(av.w, av.w, n1);
        n2  = fmaf(bv.x, bv.x, n2);
        n2  = fmaf(bv.y, bv.y, n2);
        n2  = fmaf(bv.z, bv.z, n2);
        n2  = fmaf(bv.w, bv.w, n2);
    }

    // Block reduction: warp-level then cross-warp via shared memory.
    __shared__ float s_dot[T1 / 32];
    __shared__ float s_n1[T1 / 32];
    __shared__ float s_n2[T1 / 32];

    dot = warp_sum(dot);
    n1  = warp_sum(n1);
    n2  = warp_sum(n2);

    const int lane = threadIdx.x & 31;
    const int wid  = threadIdx.x >> 5;
    if (lane == 0) {
        s_dot[wid] = dot;
        s_n1[wid]  = n1;
        s_n2[wid]  = n2;
    }
    __syncthreads();

    if (wid == 0) {
        dot = (lane < T1 / 32) ? s_dot[lane] : 0.0f;
        n1  = (lane < T1 / 32) ? s_n1[lane]  : 0.0f;
        n2  = (lane < T1 / 32) ? s_n2[lane]  : 0.0f;
        dot = warp_sum(dot);
        n1  = warp_sum(n1);
        n2  = warp_sum(n2);
        if (lane == 0) {
            g_dot[s] = dot;
            g_n1[s]  = n1;
            g_n2[s]  = n2;
        }
    }
}

// One thread per output group: cos = dot / max(||a||*||b||, eps), then mean of n.
__global__ void cos_stage2(float* __restrict__ out, int n_per_group, int n_groups) {
    const int g = blockIdx.x * blockDim.x + threadIdx.x;
    if (g >= n_groups) return;
    float acc = 0.0f;
    for (int j = 0; j < n_per_group; j++) {
        const int s = g * n_per_group + j;
        const float denom = sqrtf(g_n1[s]) * sqrtf(g_n2[s]);
        acc += g_dot[s] / fmaxf(denom, 1e-8f);
    }
    out[g] = acc / (float)n_per_group;
}

extern "C" void kernel_launch(void* const* d_in, const int* in_sizes, int n_in,
                              void* d_out, int out_size) {
    const float* x1 = (const float*)d_in[0];
    const float* x2 = (const float*)d_in[1];
    // d_in[2] is n (device int), but n is recoverable on host:
    const int N = in_sizes[0] / VEC_D;          // number of samples (512)
    const int n_groups = out_size;              // 64
    const int n_per_group = N / n_groups;       // 8
    float* out = (float*)d_out;

    cos_stage1<<<N, T1>>>(x1, x2);
    const int t2 = 64;
    cos_stage2<<<(n_groups + t2 - 1) / t2, t2>>>(out, n_per_group, n_groups);
}